// round 16
// baseline (speedup 1.0000x reference)
#include <cuda_runtime.h>
#include <cuda_fp16.h>
#include <cstdint>
#include <math.h>

#define NN 8192
#define DD 128
#define BM 128
#define BN 128
#define STR 128           // halves; 256 B row, chunk-XOR swizzle -> conflict-free + 16B aligned
#define TILES 64
#define NACT (TILES*(TILES+1)/2)   // 2080
#define NPAD 2560                  // 5*512, zero-padded
#define THREADS 512

__device__ __half X16[NN * DD];
__device__ float  g_partial[NPAD];
__device__ int    g_count;

__device__ __forceinline__ uint32_t smem_u32(const void* p) {
    uint32_t a;
    asm("{ .reg .u64 t; cvta.to.shared.u64 t, %1; cvt.u32.u64 %0, t; }" : "=r"(a) : "l"(p));
    return a;
}
__device__ __forceinline__ void cp_async16(uint32_t s, const void* g) {
    asm volatile("cp.async.cg.shared.global [%0], [%1], 16;" :: "r"(s), "l"(g) : "memory");
}
#define CP_COMMIT() asm volatile("cp.async.commit_group;" ::: "memory")
#define CP_WAIT0()  asm volatile("cp.async.wait_group 0;" ::: "memory")

__device__ __forceinline__ void ldsm_x4(uint32_t& r0, uint32_t& r1, uint32_t& r2, uint32_t& r3,
                                        uint32_t addr) {
    asm volatile("ldmatrix.sync.aligned.m8n8.x4.shared.b16 {%0,%1,%2,%3}, [%4];"
                 : "=r"(r0), "=r"(r1), "=r"(r2), "=r"(r3) : "r"(addr));
}
__device__ __forceinline__ void mma16816h(uint32_t& c0, uint32_t& c1,
                                          uint32_t a0, uint32_t a1, uint32_t a2, uint32_t a3,
                                          uint32_t b0, uint32_t b1) {
    asm volatile("mma.sync.aligned.m16n8k16.row.col.f16.f16.f16.f16 "
                 "{%0,%1}, {%2,%3,%4,%5}, {%6,%7}, {%0,%1};"
                 : "+r"(c0), "+r"(c1)
                 : "r"(a0), "r"(a1), "r"(a2), "r"(a3), "r"(b0), "r"(b1));
}

// ---------------- kernel 1: plain fp32 -> fp16 convert ----------------
__global__ void convert_kernel(const float* __restrict__ X) {
    int idx = (blockIdx.x * blockDim.x + threadIdx.x) * 4;
    float4 v = *(const float4*)&X[idx];
    __half2* o = (__half2*)&X16[idx];
    o[0] = __floats2half2_rn(v.x, v.y);
    o[1] = __floats2half2_rn(v.z, v.w);
}

__device__ __forceinline__ int tri_off(int r) { return r * TILES - (r * (r - 1)) / 2; }

// ---------------- kernel 2: fused HMMA GEMM + uniform mask + reduce ----------------
__global__ __launch_bounds__(THREADS, 2)
void sim_loss_mma(const float* __restrict__ margin,
                  const int* __restrict__ tgt,
                  float* __restrict__ out) {
    const int b = blockIdx.x;
    int by = (int)((129.0 - sqrt(16641.0 - 8.0 * (double)b)) * 0.5);
    while (tri_off(by + 1) <= b) ++by;
    while (tri_off(by) > b) --by;
    const int bx = by + (b - tri_off(by));
    const bool diag = (by == bx);

    extern __shared__ __half dsm[];
    __half* As = dsm;
    __half* Bs = dsm + BM * STR;

    __shared__ __half cs_h[BN];   // col class ids as half (0..99 exact)
    __shared__ __half cm_h[BN];
    __shared__ __half rt_h[BM];
    __shared__ __half rm_h[BM];
    __shared__ float  red[16];
    __shared__ int    flag;

    const int tid  = threadIdx.x;
    const int lane = tid & 31;
    const int wid  = tid >> 5;
    const int wm   = wid & 3;     // 4 m-blocks of 32
    const int wn   = wid >> 2;    // 4 n-blocks of 32
    const int rowBase = by * BM;
    const int colBase = bx * BN;

    const uint32_t sA = smem_u32(As);
    const uint32_t sB = smem_u32(Bs);

    // ---- one-shot full-K prefetch: 4096 x 16B over 512 threads ----
#pragma unroll
    for (int p = 0; p < 8; p++) {
        int id   = tid + p * THREADS;
        int isB  = id >> 11;
        int e    = id & 2047;
        int row  = e >> 4;
        int ch   = e & 15;
        const __half* src = &X16[(size_t)((isB ? colBase : rowBase) + row) * DD + ch * 8];
        int swch = ch ^ (row & 7);
        uint32_t dst = (isB ? sB : sA) + (uint32_t)(row * STR + swch * 8) * 2;
        cp_async16(dst, src);
    }
    CP_COMMIT();

    uint32_t acc[2][4][2];
#pragma unroll
    for (int mi = 0; mi < 2; mi++)
#pragma unroll
        for (int ni = 0; ni < 4; ni++) { acc[mi][ni][0] = 0u; acc[mi][ni][1] = 0u; }

    if (tid < 128) {
        cs_h[tid] = __float2half((float)tgt[colBase + tid]);
        cm_h[tid] = __float2half(margin[colBase + tid]);
        rt_h[tid] = __float2half((float)tgt[rowBase + tid]);
        rm_h[tid] = __float2half(margin[rowBase + tid]);
    }

    CP_WAIT0();
    __syncthreads();

    const int lrow = lane & 15;
    const int lchk = lane >> 4;

#pragma unroll
    for (int ks = 0; ks < 8; ks++) {
        uint32_t a[2][4];
#pragma unroll
        for (int mi = 0; mi < 2; mi++) {
            int row = wm * 32 + mi * 16 + lrow;
            int swch = (ks * 2 + lchk) ^ (row & 7);
            uint32_t addr = sA + (uint32_t)(row * STR + swch * 8) * 2;
            ldsm_x4(a[mi][0], a[mi][1], a[mi][2], a[mi][3], addr);
        }
        uint32_t bfr[2][4];
#pragma unroll
        for (int nb = 0; nb < 2; nb++) {
            int row = wn * 32 + nb * 16 + lrow;
            int swch = (ks * 2 + lchk) ^ (row & 7);
            uint32_t addr = sB + (uint32_t)(row * STR + swch * 8) * 2;
            ldsm_x4(bfr[nb][0], bfr[nb][1], bfr[nb][2], bfr[nb][3], addr);
        }
#pragma unroll
        for (int mi = 0; mi < 2; mi++)
#pragma unroll
            for (int ni = 0; ni < 4; ni++)
                mma16816h(acc[mi][ni][0], acc[mi][ni][1],
                          a[mi][0], a[mi][1], a[mi][2], a[mi][3],
                          bfr[ni >> 1][ni & 1], bfr[ni >> 1][2 + (ni & 1)]);
    }

    // ---- uniform blended half2 epilogue (diag handled by 0.5x tile weight) ----
    // per element: ne ? s*(g_row+g_col) : 2*max(1-s,0);  diag tiles scaled 0.5 at the end
    const int r0l = (lane >> 2);
    const int c0l = (lane & 3) * 2;
    const __half2 two2  = __float2half2_rn(2.0f);
    const __half2 zero2 = __float2half2_rn(0.0f);
    __half2 accA = zero2;
    __half2 accB = zero2;

#pragma unroll
    for (int mi = 0; mi < 2; mi++) {
        const int rA = wm * 32 + mi * 16 + r0l;
        const int rB = rA + 8;
        const __half2 trA2 = __half2half2(rt_h[rA]);
        const __half2 trB2 = __half2half2(rt_h[rB]);
        const __half2 mgA2 = __half2half2(rm_h[rA]);
        const __half2 mgB2 = __half2half2(rm_h[rB]);
#pragma unroll
        for (int ni = 0; ni < 4; ni++) {
            const int c0 = wn * 32 + ni * 8 + c0l;
            const __half2 tc2 = *(const __half2*)&cs_h[c0];
            const __half2 mc2 = *(const __half2*)&cm_h[c0];
            const __half2 sA2 = *reinterpret_cast<__half2*>(&acc[mi][ni][0]);
            const __half2 sB2 = *reinterpret_cast<__half2*>(&acc[mi][ni][1]);

            const __half2 neA = __hne2(trA2, tc2);
            const __half2 neB = __hne2(trB2, tc2);
            const __half2 gA = __hadd2(__hgt2(sA2, mgA2), __hgt2(sA2, mc2));
            const __half2 gB = __hadd2(__hgt2(sB2, mgB2), __hgt2(sB2, mc2));
            const __half2 pA = __hmax2(__hsub2(two2, __hadd2(sA2, sA2)), zero2);
            const __half2 pB = __hmax2(__hsub2(two2, __hadd2(sB2, sB2)), zero2);
            const __half2 tA = __hsub2(__hmul2(sA2, gA), pA);
            const __half2 tB = __hsub2(__hmul2(sB2, gB), pB);
            accA = __hadd2(accA, pA);
            accA = __hfma2(neA, tA, accA);
            accB = __hadd2(accB, pB);
            accB = __hfma2(neB, tB, accB);
        }
    }

    float2 fa = __half22float2(accA);
    float2 fb = __half22float2(accB);
    float local = (fa.x + fa.y) + (fb.x + fb.y);
    if (diag) local *= 0.5f;

    // ---- block reduce (16 warps) ----
#pragma unroll
    for (int off = 16; off > 0; off >>= 1)
        local += __shfl_xor_sync(0xFFFFFFFFu, local, off);
    if (lane == 0) red[wid] = local;
    __syncthreads();

    if (tid == 0) {
        float s = 0.0f;
#pragma unroll
        for (int w = 0; w < 16; w++) s += red[w];
        g_partial[b] = s;
    }

    // ---- deterministic last-block final reduce ----
    __threadfence();
    __syncthreads();
    if (tid == 0) flag = (atomicAdd(&g_count, 1) == NACT - 1) ? 1 : 0;
    __syncthreads();
    if (flag) {
        float v = 0.0f;
#pragma unroll
        for (int p = 0; p < NPAD / THREADS; p++)
            v += g_partial[tid + p * THREADS];
#pragma unroll
        for (int off = 16; off > 0; off >>= 1)
            v += __shfl_xor_sync(0xFFFFFFFFu, v, off);
        if (lane == 0) red[wid] = v;
        __syncthreads();
        if (tid == 0) {
            float s = 0.0f;
#pragma unroll
            for (int w = 0; w < 16; w++) s += red[w];
            out[0] = s / (float)NN;
            g_count = 0;
        }
    }
}

#define DSMEM_BYTES ((BM + BN) * STR * 2)   // 65536 B

extern "C" void kernel_launch(void* const* d_in, const int* in_sizes, int n_in,
                              void* d_out, int out_size) {
    const float* X      = (const float*)d_in[0];
    const float* margin = (const float*)d_in[1];
    const int*   tgt    = (const int*)d_in[2];
    float*       out    = (float*)d_out;

    static bool attr_set = false;
    if (!attr_set) {
        cudaFuncSetAttribute(sim_loss_mma, cudaFuncAttributeMaxDynamicSharedMemorySize, DSMEM_BYTES);
        attr_set = true;
    }

    convert_kernel<<<NN * DD / 4 / 256, 256>>>(X);
    sim_loss_mma<<<NACT, THREADS, DSMEM_BYTES>>>(margin, tgt, out);
}

// round 17
// speedup vs baseline: 1.2198x; 1.2198x over previous
#include <cuda_runtime.h>
#include <cuda_fp16.h>
#include <cstdint>
#include <math.h>

#define NN 8192
#define DD 128
#define BM 128
#define BN 128
#define STR 128           // halves; 256 B row, chunk-XOR swizzle -> conflict-free + 16B aligned
#define TILES 64
#define NACT (TILES*(TILES+1)/2)   // 2080
#define NPAD 2304

__device__ __half X16[NN * DD];
__device__ float  g_partial[NPAD];
__device__ int    g_count;

__device__ __forceinline__ uint32_t smem_u32(const void* p) {
    uint32_t a;
    asm("{ .reg .u64 t; cvta.to.shared.u64 t, %1; cvt.u32.u64 %0, t; }" : "=r"(a) : "l"(p));
    return a;
}
__device__ __forceinline__ void cp_async16(uint32_t s, const void* g) {
    asm volatile("cp.async.cg.shared.global [%0], [%1], 16;" :: "r"(s), "l"(g) : "memory");
}
#define CP_COMMIT() asm volatile("cp.async.commit_group;" ::: "memory")
#define CP_WAIT0()  asm volatile("cp.async.wait_group 0;" ::: "memory")

__device__ __forceinline__ void ldsm_x4(uint32_t& r0, uint32_t& r1, uint32_t& r2, uint32_t& r3,
                                        uint32_t addr) {
    asm volatile("ldmatrix.sync.aligned.m8n8.x4.shared.b16 {%0,%1,%2,%3}, [%4];"
                 : "=r"(r0), "=r"(r1), "=r"(r2), "=r"(r3) : "r"(addr));
}
__device__ __forceinline__ void mma16816h(uint32_t& c0, uint32_t& c1,
                                          uint32_t a0, uint32_t a1, uint32_t a2, uint32_t a3,
                                          uint32_t b0, uint32_t b1) {
    asm volatile("mma.sync.aligned.m16n8k16.row.col.f16.f16.f16.f16 "
                 "{%0,%1}, {%2,%3,%4,%5}, {%6,%7}, {%0,%1};"
                 : "+r"(c0), "+r"(c1)
                 : "r"(a0), "r"(a1), "r"(a2), "r"(a3), "r"(b0), "r"(b1));
}

// ---------------- kernel 1: plain fp32 -> fp16 convert ----------------
__global__ void convert_kernel(const float* __restrict__ X) {
    int idx = (blockIdx.x * blockDim.x + threadIdx.x) * 4;
    float4 v = *(const float4*)&X[idx];
    __half2* o = (__half2*)&X16[idx];
    o[0] = __floats2half2_rn(v.x, v.y);
    o[1] = __floats2half2_rn(v.z, v.w);
}

__device__ __forceinline__ int tri_off(int r) { return r * TILES - (r * (r - 1)) / 2; }

// ---------------- kernel 2: fused HMMA GEMM + uniform mask + reduce ----------------
__global__ __launch_bounds__(256, 3)
void sim_loss_mma(const float* __restrict__ margin,
                  const int* __restrict__ tgt,
                  float* __restrict__ out) {
    const int b = blockIdx.x;
    int by = (int)((129.0 - sqrt(16641.0 - 8.0 * (double)b)) * 0.5);
    while (tri_off(by + 1) <= b) ++by;
    while (tri_off(by) > b) --by;
    const int bx = by + (b - tri_off(by));
    const bool diag = (by == bx);

    extern __shared__ __half dsm[];
    __half* As = dsm;
    __half* Bs = dsm + BM * STR;

    __shared__ __half cs_h[BN];   // col class ids as half (0..99 exact)
    __shared__ __half cm_h[BN];
    __shared__ __half rt_h[BM];
    __shared__ __half rm_h[BM];
    __shared__ float  red[8];
    __shared__ int    flag;

    const int tid  = threadIdx.x;
    const int lane = tid & 31;
    const int wid  = tid >> 5;
    const int wm   = wid & 1;
    const int wn   = wid >> 1;
    const int rowBase = by * BM;
    const int colBase = bx * BN;

    const uint32_t sA = smem_u32(As);
    const uint32_t sB = smem_u32(Bs);

#pragma unroll
    for (int p = 0; p < 16; p++) {
        int id   = tid + p * 256;
        int isB  = id >> 11;
        int e    = id & 2047;
        int row  = e >> 4;
        int ch   = e & 15;
        const __half* src = &X16[(size_t)((isB ? colBase : rowBase) + row) * DD + ch * 8];
        int swch = ch ^ (row & 7);
        uint32_t dst = (isB ? sB : sA) + (uint32_t)(row * STR + swch * 8) * 2;
        cp_async16(dst, src);
    }
    CP_COMMIT();

    uint32_t acc[4][4][2];
#pragma unroll
    for (int mi = 0; mi < 4; mi++)
#pragma unroll
        for (int ni = 0; ni < 4; ni++) { acc[mi][ni][0] = 0u; acc[mi][ni][1] = 0u; }

    if (tid < 128) {
        cs_h[tid] = __float2half((float)tgt[colBase + tid]);
        cm_h[tid] = __float2half(margin[colBase + tid]);
        rt_h[tid] = __float2half((float)tgt[rowBase + tid]);
        rm_h[tid] = __float2half(margin[rowBase + tid]);
    }

    CP_WAIT0();
    __syncthreads();

    const int lrow = lane & 15;
    const int lchk = lane >> 4;

#pragma unroll
    for (int ks = 0; ks < 8; ks++) {
        uint32_t a[4][4];
#pragma unroll
        for (int mi = 0; mi < 4; mi++) {
            int row = wm * 64 + mi * 16 + lrow;
            int swch = (ks * 2 + lchk) ^ (row & 7);
            uint32_t addr = sA + (uint32_t)(row * STR + swch * 8) * 2;
            ldsm_x4(a[mi][0], a[mi][1], a[mi][2], a[mi][3], addr);
        }
        uint32_t bfr[2][4];
#pragma unroll
        for (int nb = 0; nb < 2; nb++) {
            int row = wn * 32 + nb * 16 + lrow;
            int swch = (ks * 2 + lchk) ^ (row & 7);
            uint32_t addr = sB + (uint32_t)(row * STR + swch * 8) * 2;
            ldsm_x4(bfr[nb][0], bfr[nb][1], bfr[nb][2], bfr[nb][3], addr);
        }
#pragma unroll
        for (int mi = 0; mi < 4; mi++)
#pragma unroll
            for (int ni = 0; ni < 4; ni++)
                mma16816h(acc[mi][ni][0], acc[mi][ni][1],
                          a[mi][0], a[mi][1], a[mi][2], a[mi][3],
                          bfr[ni >> 1][ni & 1], bfr[ni >> 1][2 + (ni & 1)]);
    }

    // ---- uniform blended half2 epilogue, 4 independent chains ----
    // per element: ne ? s*(g_row+g_col) : 2*relu(1-s); diag tiles weighted 0.5
    const int r0l = (lane >> 2);
    const int c0l = (lane & 3) * 2;
    const __half2 two2   = __float2half2_rn(2.0f);
    const __half2 ntwo2  = __float2half2_rn(-2.0f);
    const __half2 zero2  = __float2half2_rn(0.0f);
    __half2 accA0 = zero2, accA1 = zero2, accB0 = zero2, accB1 = zero2;

#pragma unroll
    for (int mi = 0; mi < 4; mi++) {
        const int rA = wm * 64 + mi * 16 + r0l;
        const int rB = rA + 8;
        const __half2 trA2 = __half2half2(rt_h[rA]);
        const __half2 trB2 = __half2half2(rt_h[rB]);
        const __half2 mgA2 = __half2half2(rm_h[rA]);
        const __half2 mgB2 = __half2half2(rm_h[rB]);
#pragma unroll
        for (int ni = 0; ni < 4; ni++) {
            const int c0 = wn * 32 + ni * 8 + c0l;
            const __half2 tc2 = *(const __half2*)&cs_h[c0];
            const __half2 mc2 = *(const __half2*)&cm_h[c0];
            const __half2 sA2 = *reinterpret_cast<__half2*>(&acc[mi][ni][0]);
            const __half2 sB2 = *reinterpret_cast<__half2*>(&acc[mi][ni][1]);

            const __half2 neA = __hne2(trA2, tc2);
            const __half2 neB = __hne2(trB2, tc2);
            const __half2 gA = __hadd2(__hgt2(sA2, mgA2), __hgt2(sA2, mc2));
            const __half2 gB = __hadd2(__hgt2(sB2, mgB2), __hgt2(sB2, mc2));
            const __half2 pA = __hmax2(__hfma2(sA2, ntwo2, two2), zero2);  // 2*relu(1-s)
            const __half2 pB = __hmax2(__hfma2(sB2, ntwo2, two2), zero2);
            const __half2 tA = __hsub2(__hmul2(sA2, gA), pA);
            const __half2 tB = __hsub2(__hmul2(sB2, gB), pB);
            if (ni & 1) {
                accA1 = __hadd2(accA1, pA);
                accA1 = __hfma2(neA, tA, accA1);
                accB1 = __hadd2(accB1, pB);
                accB1 = __hfma2(neB, tB, accB1);
            } else {
                accA0 = __hadd2(accA0, pA);
                accA0 = __hfma2(neA, tA, accA0);
                accB0 = __hadd2(accB0, pB);
                accB0 = __hfma2(neB, tB, accB0);
            }
        }
    }

    float2 fa0 = __half22float2(accA0);
    float2 fa1 = __half22float2(accA1);
    float2 fb0 = __half22float2(accB0);
    float2 fb1 = __half22float2(accB1);
    float local = (fa0.x + fa0.y) + (fa1.x + fa1.y) + (fb0.x + fb0.y) + (fb1.x + fb1.y);
    if (diag) local *= 0.5f;

    // ---- block reduce ----
#pragma unroll
    for (int off = 16; off > 0; off >>= 1)
        local += __shfl_xor_sync(0xFFFFFFFFu, local, off);
    if (lane == 0) red[wid] = local;
    __syncthreads();

    if (tid == 0) {
        float s = 0.0f;
#pragma unroll
        for (int w = 0; w < 8; w++) s += red[w];
        g_partial[b] = s;
    }

    // ---- deterministic last-block final reduce ----
    __threadfence();
    __syncthreads();
    if (tid == 0) flag = (atomicAdd(&g_count, 1) == NACT - 1) ? 1 : 0;
    __syncthreads();
    if (flag) {
        float v = 0.0f;
#pragma unroll
        for (int p = 0; p < NPAD / 256; p++)
            v += g_partial[tid + p * 256];
#pragma unroll
        for (int off = 16; off > 0; off >>= 1)
            v += __shfl_xor_sync(0xFFFFFFFFu, v, off);
        if (lane == 0) red[wid] = v;
        __syncthreads();
        if (tid == 0) {
            float s = 0.0f;
#pragma unroll
            for (int w = 0; w < 8; w++) s += red[w];
            out[0] = s / (float)NN;
            g_count = 0;
        }
    }
}

#define DSMEM_BYTES ((BM + BN) * STR * 2)   // 65536 B

extern "C" void kernel_launch(void* const* d_in, const int* in_sizes, int n_in,
                              void* d_out, int out_size) {
    const float* X      = (const float*)d_in[0];
    const float* margin = (const float*)d_in[1];
    const int*   tgt    = (const int*)d_in[2];
    float*       out    = (float*)d_out;

    static bool attr_set = false;
    if (!attr_set) {
        cudaFuncSetAttribute(sim_loss_mma, cudaFuncAttributeMaxDynamicSharedMemorySize, DSMEM_BYTES);
        attr_set = true;
    }

    convert_kernel<<<NN * DD / 4 / 256, 256>>>(X);
    sim_loss_mma<<<NACT, 256, DSMEM_BYTES>>>(margin, tgt, out);
}